// round 16
// baseline (speedup 1.0000x reference)
#include <cuda_runtime.h>
#include <cuda_fp16.h>
#include <cstdint>

#define N_MAX 100000
#define E_MAX 1600000
#define D 256

// ---- scratch (static device globals; zero-initialized at load, re-zeroed by gemm epilogue) ----
__device__ int      g_out_deg[N_MAX];
__device__ int      g_in_deg[N_MAX];
__device__ float    g_post[N_MAX];               // in_deg^-0.5
__device__ int      g_row_ptr[N_MAX + 1];
__device__ int      g_rank[E_MAX];               // edge rank within dst bucket
__device__ int      g_csr_src[E_MAX];
__device__ unsigned long long g_scan_state[128]; // (flag<<32)|value for lookback
__device__ int      g_scan_done;                 // # scan blocks finished
__device__ __half   g_agg16[(size_t)N_MAX * D];  // aggregated features, fp16
__device__ __half   g_feat16[(size_t)N_MAX * D]; // pre-scaled fp16 features
__device__ __half   g_wt16[D * D];               // W^T as fp16, [n][k]

// ======================= kernels =======================
__global__ void k_deg(const int* __restrict__ src, const int* __restrict__ dst, int e) {
    int i = (blockIdx.x * blockDim.x + threadIdx.x) * 2;
    if (i + 1 < e) {
        int d0 = dst[i], d1 = dst[i + 1];
        int s0 = src[i], s1 = src[i + 1];
        int r0 = atomicAdd(&g_in_deg[d0], 1);
        int r1 = atomicAdd(&g_in_deg[d1], 1);
        atomicAdd(&g_out_deg[s0], 1);
        atomicAdd(&g_out_deg[s1], 1);
        g_rank[i] = r0;
        g_rank[i + 1] = r1;
    } else if (i < e) {
        g_rank[i] = atomicAdd(&g_in_deg[dst[i]], 1);
        atomicAdd(&g_out_deg[src[i]], 1);
    }
}

// Fat kernel: blocks [0,nb) = scan; [nb,nb+fb) = feat->fp16; [..,+64) = W cvt; rest = CSR fill.
__global__ __launch_bounds__(1024) void k_mid(const float4* __restrict__ feat4,
                                              const float* __restrict__ W,
                                              const int* __restrict__ src,
                                              const int* __restrict__ dst,
                                              int n, int e, int nb, int fb) {
    __shared__ int s[1088];
    const int b = blockIdx.x;

    if (b < nb) {
        // ---- scan: shfl block-scan + warp-parallel lookback ----
        __shared__ int s_prev;
        const int lane = threadIdx.x & 31;
        const int wrp  = threadIdx.x >> 5;
        const int i = b * 1024 + threadIdx.x;
        int v = (i < n) ? g_in_deg[i] : 0;
        if (i < n) g_post[i] = rsqrtf((float)max(v, 1));

        int x = v;
#pragma unroll
        for (int o = 1; o < 32; o <<= 1) {
            int y = __shfl_up_sync(0xFFFFFFFFu, x, o);
            if (lane >= o) x += y;
        }
        if (lane == 31) s[wrp] = x;
        __syncthreads();
        if (wrp == 0) {
            int t = s[lane];
#pragma unroll
            for (int o = 1; o < 32; o <<= 1) {
                int y = __shfl_up_sync(0xFFFFFFFFu, t, o);
                if (lane >= o) t += y;
            }
            s[lane] = t;
        }
        __syncthreads();
        int incl  = x + (wrp ? s[wrp - 1] : 0);
        int total = s[31];

        if (wrp == 0) {
            if (b == 0) {
                if (lane == 0) {
                    atomicExch(&g_scan_state[0], (2ULL << 32) | (unsigned)total);
                    s_prev = 0;
                }
            } else {
                if (lane == 0)
                    atomicExch(&g_scan_state[b], (1ULL << 32) | (unsigned)total);
                int sum = 0;
                int start = b - 1;
                while (true) {
                    int idx = start - lane;
                    int flag = 2, val = 0;
                    if (idx >= 0) {
                        unsigned long long w;
                        do { w = atomicAdd(&g_scan_state[idx], 0ULL); } while ((w >> 32) == 0);
                        flag = (int)(w >> 32);
                        val  = (int)(unsigned)w;
                    }
                    unsigned m = __ballot_sync(0xFFFFFFFFu, flag == 2);
                    int lim = m ? (__ffs(m) - 1) : 31;
                    int contrib = (lane <= lim) ? val : 0;
#pragma unroll
                    for (int o = 16; o; o >>= 1)
                        contrib += __shfl_xor_sync(0xFFFFFFFFu, contrib, o);
                    sum += contrib;
                    if (m) break;
                    start -= 32;
                }
                if (lane == 0) {
                    atomicExch(&g_scan_state[b], (2ULL << 32) | (unsigned)(sum + total));
                    s_prev = sum;
                }
            }
        }
        __syncthreads();
        int prev = s_prev;
        if (i < n) g_row_ptr[i + 1] = prev + incl;
        if (i == 0) g_row_ptr[0] = 0;
        __syncthreads();
        if (threadIdx.x == 0) {
            __threadfence();
            atomicAdd(&g_scan_done, 1);
        }
    } else if (b < nb + fb) {
        int idx = (b - nb) * 1024 + threadIdx.x;
        if (idx < n * 32) {
            int node = idx >> 5;
            float p = rsqrtf((float)max(g_out_deg[node], 1));
            float4 v0 = feat4[(size_t)idx * 2];
            float4 v1 = feat4[(size_t)idx * 2 + 1];
            __half2 h[4];
            h[0] = __floats2half2_rn(v0.x * p, v0.y * p);
            h[1] = __floats2half2_rn(v0.z * p, v0.w * p);
            h[2] = __floats2half2_rn(v1.x * p, v1.y * p);
            h[3] = __floats2half2_rn(v1.z * p, v1.w * p);
            *(uint4*)&g_feat16[(size_t)idx * 8] = *(uint4*)h;
        }
    } else if (b < nb + fb + 64) {
        float* sh = (float*)s;   // 32 x 33
        int bt = b - nb - fb;
        int bx = bt & 7, by = bt >> 3;
        int tx = threadIdx.x & 31, ty = threadIdx.x >> 5;
        sh[ty * 33 + tx] = W[(size_t)(by * 32 + ty) * D + bx * 32 + tx];
        __syncthreads();
        g_wt16[(size_t)(bx * 32 + ty) * D + by * 32 + tx] = __float2half_rn(sh[tx * 33 + ty]);
    } else {
        if (threadIdx.x == 0) {
            while (atomicAdd(&g_scan_done, 0) < nb) { }
        }
        __syncthreads();
        int i = (b - nb - fb - 64) * 1024 + threadIdx.x;
        if (i < e) {
            int d = dst[i];
            g_csr_src[g_row_ptr[d] + g_rank[i]] = src[i];
        }
    }
}

// ======================= aggregation (persistent, 2-edge pipeline, 32 regs) ==============
__device__ __forceinline__ unsigned long long pack_f2(float2 f) {
    unsigned long long r;
    asm("mov.b64 %0, {%1, %2};" : "=l"(r) : "f"(f.x), "f"(f.y));
    return r;
}

__device__ __forceinline__ void accpair(unsigned long long* acc, uint4 u0, uint4 u1) {
    __half2* h0 = (__half2*)&u0;
    __half2* h1 = (__half2*)&u1;
#pragma unroll
    for (int i = 0; i < 4; i++) {
        __half2 p = __hadd2(h0[i], h1[i]);
        float2 fp = __half22float2(p);
        asm("add.rn.f32x2 %0, %0, %1;" : "+l"(acc[i]) : "l"(pack_f2(fp)));
    }
}

__device__ __forceinline__ void accone(unsigned long long* acc, uint4 u0) {
    __half2* h0 = (__half2*)&u0;
#pragma unroll
    for (int i = 0; i < 4; i++) {
        float2 fp = __half22float2(h0[i]);
        asm("add.rn.f32x2 %0, %0, %1;" : "+l"(acc[i]) : "l"(pack_f2(fp)));
    }
}

__global__ __launch_bounds__(256) void k_agg(int n, int vblocks) {
    const int lane = threadIdx.x & 31;
    const int wid  = threadIdx.x >> 5;
    const uint4* f = (const uint4*)g_feat16;  // 32 uint4 per row
    for (int vb = blockIdx.x; vb < vblocks; vb += gridDim.x) {
        int node = vb * 8 + wid;
        if (node >= n) continue;
        int beg = g_row_ptr[node];
        int end = g_row_ptr[node + 1];
        unsigned long long acc[4] = {0ULL, 0ULL, 0ULL, 0ULL};
        int j = beg;
        int i0 = 0, i1 = 0;
        if (j + 2 <= end) { i0 = g_csr_src[j]; i1 = g_csr_src[j + 1]; }
        while (j + 2 <= end) {
            uint4 u0 = f[(size_t)i0 * 32 + lane];
            uint4 u1 = f[(size_t)i1 * 32 + lane];
            j += 2;
            if (j + 2 <= end) { i0 = g_csr_src[j]; i1 = g_csr_src[j + 1]; }
            accpair(acc, u0, u1);
        }
        if (j < end) {
            accone(acc, f[(size_t)g_csr_src[j] * 32 + lane]);
        }
        __half2 h[4];
#pragma unroll
        for (int i = 0; i < 4; i++) {
            float lo, hi;
            asm("mov.b64 {%0, %1}, %2;" : "=f"(lo), "=f"(hi) : "l"(acc[i]));
            h[i] = __floats2half2_rn(lo, hi);
        }
        *(uint4*)&g_agg16[(size_t)node * D + lane * 8] = *(uint4*)h;
    }
}

// ======================= fp16 warp-MMA GEMM (512 threads, 16 warps, warp tile 64x16) ====
#define SAB_STRIDE 40

__device__ __forceinline__ void mma_f16(float* c, const uint32_t* a, const uint32_t* b) {
    asm volatile(
        "mma.sync.aligned.m16n8k16.row.col.f32.f16.f16.f32 "
        "{%0,%1,%2,%3}, {%4,%5,%6,%7}, {%8,%9}, {%0,%1,%2,%3};"
        : "+f"(c[0]), "+f"(c[1]), "+f"(c[2]), "+f"(c[3])
        : "r"(a[0]), "r"(a[1]), "r"(a[2]), "r"(a[3]), "r"(b[0]), "r"(b[1]));
}

__device__ __forceinline__ void ldsm_x4(uint32_t& r0, uint32_t& r1, uint32_t& r2,
                                        uint32_t& r3, uint32_t addr) {
    asm volatile("ldmatrix.sync.aligned.m8n8.x4.shared.b16 {%0,%1,%2,%3}, [%4];"
                 : "=r"(r0), "=r"(r1), "=r"(r2), "=r"(r3) : "r"(addr));
}

__global__ __launch_bounds__(512, 3) void k_gemm_mma(const float* __restrict__ bias,
                                                     float* __restrict__ out, int n) {
    __shared__ __half sA[2][128 * SAB_STRIDE];
    __shared__ __half sB[2][128 * SAB_STRIDE];

    const int tid = threadIdx.x;
    const int wid = tid >> 5;       // 0..15
    const int lid = tid & 31;
    const int g   = lid >> 2;
    const int t   = lid & 3;
    const int wm  = wid & 1;        // 2 m-warps (64 rows each)
    const int wn  = wid >> 1;       // 8 n-warps (16 cols each)

    const int row0 = blockIdx.y * 128;
    const int n0   = blockIdx.x * 128;
    const int arows = min(128, n - row0);

    const int st_r  = tid >> 2;     // 0..127
    const int st_c8 = (tid & 3) * 8;

    const int lm_r = lid & 15;
    const int lm_c = (lid >> 4) * 8;

    float acc[4][2][4];
#pragma unroll
    for (int mf = 0; mf < 4; mf++)
#pragma unroll
        for (int nf = 0; nf < 2; nf++)
#pragma unroll
            for (int r = 0; r < 4; r++) acc[mf][nf][r] = 0.f;

    uint4 ua, ub;
    {
        int r = st_r;
        ua = make_uint4(0, 0, 0, 0);
        if (r < arows) ua = *(const uint4*)&g_agg16[(size_t)(row0 + r) * D + st_c8];
        ub = *(const uint4*)&g_wt16[(size_t)(n0 + r) * D + st_c8];
        *(uint4*)&sA[0][r * SAB_STRIDE + st_c8] = ua;
        *(uint4*)&sB[0][r * SAB_STRIDE + st_c8] = ub;
    }
    __syncthreads();

    for (int kc = 0; kc < 8; kc++) {
        const int cur = kc & 1;
        if (kc < 7) {
            const int kb = (kc + 1) * 32;
            int r = st_r;
            ua = make_uint4(0, 0, 0, 0);
            if (r < arows) ua = *(const uint4*)&g_agg16[(size_t)(row0 + r) * D + kb + st_c8];
            ub = *(const uint4*)&g_wt16[(size_t)(n0 + r) * D + kb + st_c8];
        }
#pragma unroll
        for (int ks = 0; ks < 2; ks++) {
            const int k0 = ks * 16;
            uint32_t af[4][4], bf[2][2];
#pragma unroll
            for (int mf = 0; mf < 4; mf++) {
                int mrow = wm * 64 + mf * 16 + lm_r;
                uint32_t addr = (uint32_t)__cvta_generic_to_shared(
                    &sA[cur][mrow * SAB_STRIDE + k0 + lm_c]);
                ldsm_x4(af[mf][0], af[mf][1], af[mf][2], af[mf][3], addr);
            }
            {
                int nrow = wn * 16 + lm_r;
                uint32_t addr = (uint32_t)__cvta_generic_to_shared(
                    &sB[cur][nrow * SAB_STRIDE + k0 + lm_c]);
                ldsm_x4(bf[0][0], bf[1][0], bf[0][1], bf[1][1], addr);
            }
#pragma unroll
            for (int mf = 0; mf < 4; mf++)
#pragma unroll
                for (int nf = 0; nf < 2; nf++)
                    mma_f16(acc[mf][nf], af[mf], bf[nf]);
        }
        if (kc < 7) {
            const int nxt = cur ^ 1;
            int r = st_r;
            *(uint4*)&sA[nxt][r * SAB_STRIDE + st_c8] = ua;
            *(uint4*)&sB[nxt][r * SAB_STRIDE + st_c8] = ub;
            __syncthreads();
        }
    }

#pragma unroll
    for (int mf = 0; mf < 4; mf++) {
        int r0 = row0 + wm * 64 + mf * 16 + g;
        int r1 = r0 + 8;
        float post0 = 0.f, post1 = 0.f;
        if (r0 < n) post0 = g_post[r0];
        if (r1 < n) post1 = g_post[r1];
#pragma unroll
        for (int nf = 0; nf < 2; nf++) {
            int c = n0 + wn * 16 + nf * 8 + t * 2;
            float2 b2 = *(const float2*)&bias[c];
            if (r0 < n) {
                float2 v;
                v.x = acc[mf][nf][0] * post0 + b2.x;
                v.y = acc[mf][nf][1] * post0 + b2.y;
                *(float2*)&out[(size_t)r0 * D + c] = v;
            }
            if (r1 < n) {
                float2 v;
                v.x = acc[mf][nf][2] * post1 + b2.x;
                v.y = acc[mf][nf][3] * post1 + b2.y;
                *(float2*)&out[(size_t)r1 * D + c] = v;
            }
        }
    }

    // ---- zero scratch counters for the NEXT replay ----
    if (blockIdx.x == 0) {
        for (int i = tid; i < 128; i += 512) {
            int r = row0 + i;
            if (r < n) { g_in_deg[r] = 0; g_out_deg[r] = 0; }
        }
        if (blockIdx.y == 0) {
            if (tid < 128) g_scan_state[tid] = 0ULL;
            if (tid == 128) g_scan_done = 0;
        }
    }
}

// ======================= launch =======================
extern "C" void kernel_launch(void* const* d_in, const int* in_sizes, int n_in,
                              void* d_out, int out_size) {
    const float* feat   = (const float*)d_in[0];
    const int*   src    = (const int*)d_in[1];
    const int*   dst    = (const int*)d_in[2];
    const float* weight = (const float*)d_in[3];
    const float* bias   = (const float*)d_in[4];
    float*       out    = (float*)d_out;

    int n = in_sizes[0] / D;   // 100000
    int e = in_sizes[1];       // 1600000

    int nb = (n + 1023) / 1024;           // 98 scan blocks
    int fb = (n * 32 + 1023) / 1024;      // 3125 feat-convert blocks
    int wb = 64;                          // W transpose blocks
    int eb = (e + 1023) / 1024;           // 1563 fill blocks
    int degb = ((e + 1) / 2 + 255) / 256;

    k_deg<<<degb, 256>>>(src, dst, e);                                       // 0
    k_mid<<<nb + fb + wb + eb, 1024>>>((const float4*)feat, weight,
                                       src, dst, n, e, nb, fb);              // 1
    k_agg<<<1184, 256>>>(n, (n + 7) / 8);                                    // 2
    dim3 gg(2, (n + 127) / 128);
    k_gemm_mma<<<gg, 512>>>(bias, out, n);                                   // 3  <- profiled
}

// round 17
// speedup vs baseline: 2.0031x; 2.0031x over previous
#include <cuda_runtime.h>
#include <cuda_fp16.h>
#include <cstdint>

#define N_MAX 100000
#define E_MAX 1600000
#define D 256

// ---- scratch (static device globals; zero-initialized at load, re-zeroed by gemm epilogue) ----
__device__ int      g_out_deg[N_MAX];
__device__ int      g_in_deg[N_MAX];
__device__ float    g_post[N_MAX];               // in_deg^-0.5
__device__ int      g_row_ptr[N_MAX + 1];
__device__ int      g_rank[E_MAX];               // edge rank within dst bucket
__device__ int      g_csr_src[E_MAX];
__device__ unsigned long long g_scan_state[128]; // (flag<<32)|value for lookback
__device__ int      g_scan_done;                 // # scan blocks finished
__device__ __half   g_agg16[(size_t)N_MAX * D];  // aggregated features, fp16
__device__ __half   g_feat16[(size_t)N_MAX * D]; // pre-scaled fp16 features
__device__ __half   g_wt16[D * D];               // W^T as fp16, [n][k]

// ======================= kernels =======================
__global__ void k_deg(const int* __restrict__ src, const int* __restrict__ dst, int e) {
    int i = (blockIdx.x * blockDim.x + threadIdx.x) * 2;
    if (i + 1 < e) {
        int d0 = dst[i], d1 = dst[i + 1];
        int s0 = src[i], s1 = src[i + 1];
        int r0 = atomicAdd(&g_in_deg[d0], 1);
        int r1 = atomicAdd(&g_in_deg[d1], 1);
        atomicAdd(&g_out_deg[s0], 1);
        atomicAdd(&g_out_deg[s1], 1);
        g_rank[i] = r0;
        g_rank[i + 1] = r1;
    } else if (i < e) {
        g_rank[i] = atomicAdd(&g_in_deg[dst[i]], 1);
        atomicAdd(&g_out_deg[src[i]], 1);
    }
}

// Fat kernel: blocks [0,nb) = scan; [nb,nb+fb) = feat->fp16; [..,+64) = W cvt; rest = CSR fill.
__global__ __launch_bounds__(1024) void k_mid(const float4* __restrict__ feat4,
                                              const float* __restrict__ W,
                                              const int* __restrict__ src,
                                              const int* __restrict__ dst,
                                              int n, int e, int nb, int fb) {
    __shared__ int s[1088];
    const int b = blockIdx.x;

    if (b < nb) {
        __shared__ int s_prev;
        const int lane = threadIdx.x & 31;
        const int wrp  = threadIdx.x >> 5;
        const int i = b * 1024 + threadIdx.x;
        int v = (i < n) ? g_in_deg[i] : 0;
        if (i < n) g_post[i] = rsqrtf((float)max(v, 1));

        int x = v;
#pragma unroll
        for (int o = 1; o < 32; o <<= 1) {
            int y = __shfl_up_sync(0xFFFFFFFFu, x, o);
            if (lane >= o) x += y;
        }
        if (lane == 31) s[wrp] = x;
        __syncthreads();
        if (wrp == 0) {
            int t = s[lane];
#pragma unroll
            for (int o = 1; o < 32; o <<= 1) {
                int y = __shfl_up_sync(0xFFFFFFFFu, t, o);
                if (lane >= o) t += y;
            }
            s[lane] = t;
        }
        __syncthreads();
        int incl  = x + (wrp ? s[wrp - 1] : 0);
        int total = s[31];

        if (wrp == 0) {
            if (b == 0) {
                if (lane == 0) {
                    atomicExch(&g_scan_state[0], (2ULL << 32) | (unsigned)total);
                    s_prev = 0;
                }
            } else {
                if (lane == 0)
                    atomicExch(&g_scan_state[b], (1ULL << 32) | (unsigned)total);
                int sum = 0;
                int start = b - 1;
                while (true) {
                    int idx = start - lane;
                    int flag = 2, val = 0;
                    if (idx >= 0) {
                        unsigned long long w;
                        do { w = atomicAdd(&g_scan_state[idx], 0ULL); } while ((w >> 32) == 0);
                        flag = (int)(w >> 32);
                        val  = (int)(unsigned)w;
                    }
                    unsigned m = __ballot_sync(0xFFFFFFFFu, flag == 2);
                    int lim = m ? (__ffs(m) - 1) : 31;
                    int contrib = (lane <= lim) ? val : 0;
#pragma unroll
                    for (int o = 16; o; o >>= 1)
                        contrib += __shfl_xor_sync(0xFFFFFFFFu, contrib, o);
                    sum += contrib;
                    if (m) break;
                    start -= 32;
                }
                if (lane == 0) {
                    atomicExch(&g_scan_state[b], (2ULL << 32) | (unsigned)(sum + total));
                    s_prev = sum;
                }
            }
        }
        __syncthreads();
        int prev = s_prev;
        if (i < n) g_row_ptr[i + 1] = prev + incl;
        if (i == 0) g_row_ptr[0] = 0;
        __syncthreads();
        if (threadIdx.x == 0) {
            __threadfence();
            atomicAdd(&g_scan_done, 1);
        }
    } else if (b < nb + fb) {
        int idx = (b - nb) * 1024 + threadIdx.x;
        if (idx < n * 32) {
            int node = idx >> 5;
            float p = rsqrtf((float)max(g_out_deg[node], 1));
            float4 v0 = feat4[(size_t)idx * 2];
            float4 v1 = feat4[(size_t)idx * 2 + 1];
            __half2 h[4];
            h[0] = __floats2half2_rn(v0.x * p, v0.y * p);
            h[1] = __floats2half2_rn(v0.z * p, v0.w * p);
            h[2] = __floats2half2_rn(v1.x * p, v1.y * p);
            h[3] = __floats2half2_rn(v1.z * p, v1.w * p);
            *(uint4*)&g_feat16[(size_t)idx * 8] = *(uint4*)h;
        }
    } else if (b < nb + fb + 64) {
        float* sh = (float*)s;   // 32 x 33
        int bt = b - nb - fb;
        int bx = bt & 7, by = bt >> 3;
        int tx = threadIdx.x & 31, ty = threadIdx.x >> 5;
        sh[ty * 33 + tx] = W[(size_t)(by * 32 + ty) * D + bx * 32 + tx];
        __syncthreads();
        g_wt16[(size_t)(bx * 32 + ty) * D + by * 32 + tx] = __float2half_rn(sh[tx * 33 + ty]);
    } else {
        if (threadIdx.x == 0) {
            while (atomicAdd(&g_scan_done, 0) < nb) { }
        }
        __syncthreads();
        int i = (b - nb - fb - 64) * 1024 + threadIdx.x;
        if (i < e) {
            int d = dst[i];
            g_csr_src[g_row_ptr[d] + g_rank[i]] = src[i];
        }
    }
}

// ======================= aggregation (persistent, 2-edge pipeline, 32 regs) ==============
__device__ __forceinline__ unsigned long long pack_f2(float2 f) {
    unsigned long long r;
    asm("mov.b64 %0, {%1, %2};" : "=l"(r) : "f"(f.x), "f"(f.y));
    return r;
}

__device__ __forceinline__ void accpair(unsigned long long* acc, uint4 u0, uint4 u1) {
    __half2* h0 = (__half2*)&u0;
    __half2* h1 = (__half2*)&u1;
#pragma unroll
    for (int i = 0; i < 4; i++) {
        __half2 p = __hadd2(h0[i], h1[i]);
        float2 fp = __half22float2(p);
        asm("add.rn.f32x2 %0, %0, %1;" : "+l"(acc[i]) : "l"(pack_f2(fp)));
    }
}

__device__ __forceinline__ void accone(unsigned long long* acc, uint4 u0) {
    __half2* h0 = (__half2*)&u0;
#pragma unroll
    for (int i = 0; i < 4; i++) {
        float2 fp = __half22float2(h0[i]);
        asm("add.rn.f32x2 %0, %0, %1;" : "+l"(acc[i]) : "l"(pack_f2(fp)));
    }
}

__global__ __launch_bounds__(256) void k_agg(int n, int vblocks) {
    const int lane = threadIdx.x & 31;
    const int wid  = threadIdx.x >> 5;
    const uint4* f = (const uint4*)g_feat16;
    for (int vb = blockIdx.x; vb < vblocks; vb += gridDim.x) {
        int node = vb * 8 + wid;
        if (node >= n) continue;
        int beg = g_row_ptr[node];
        int end = g_row_ptr[node + 1];
        unsigned long long acc[4] = {0ULL, 0ULL, 0ULL, 0ULL};
        int j = beg;
        int i0 = 0, i1 = 0;
        if (j + 2 <= end) { i0 = g_csr_src[j]; i1 = g_csr_src[j + 1]; }
        while (j + 2 <= end) {
            uint4 u0 = f[(size_t)i0 * 32 + lane];
            uint4 u1 = f[(size_t)i1 * 32 + lane];
            j += 2;
            if (j + 2 <= end) { i0 = g_csr_src[j]; i1 = g_csr_src[j + 1]; }
            accpair(acc, u0, u1);
        }
        if (j < end) {
            accone(acc, f[(size_t)g_csr_src[j] * 32 + lane]);
        }
        __half2 h[4];
#pragma unroll
        for (int i = 0; i < 4; i++) {
            float lo, hi;
            asm("mov.b64 {%0, %1}, %2;" : "=f"(lo), "=f"(hi) : "l"(acc[i]));
            h[i] = __floats2half2_rn(lo, hi);
        }
        *(uint4*)&g_agg16[(size_t)node * D + lane * 8] = *(uint4*)h;
    }
}

// ======================= fp16 warp-MMA GEMM (256 thr, 64x32 warp tile, 4-stage cp.async) =
#define SAB_STRIDE 40
#define TILE_H    (128 * SAB_STRIDE)            // halves per tile per array
#define SMEM_GEMM (4 * 2 * TILE_H * 2)          // 4 stages x (A+B) x 2B = 81920

__device__ __forceinline__ void mma_f16(float* c, const uint32_t* a, const uint32_t* b) {
    asm volatile(
        "mma.sync.aligned.m16n8k16.row.col.f32.f16.f16.f32 "
        "{%0,%1,%2,%3}, {%4,%5,%6,%7}, {%8,%9}, {%0,%1,%2,%3};"
        : "+f"(c[0]), "+f"(c[1]), "+f"(c[2]), "+f"(c[3])
        : "r"(a[0]), "r"(a[1]), "r"(a[2]), "r"(a[3]), "r"(b[0]), "r"(b[1]));
}

__device__ __forceinline__ void ldsm_x4(uint32_t& r0, uint32_t& r1, uint32_t& r2,
                                        uint32_t& r3, uint32_t addr) {
    asm volatile("ldmatrix.sync.aligned.m8n8.x4.shared.b16 {%0,%1,%2,%3}, [%4];"
                 : "=r"(r0), "=r"(r1), "=r"(r2), "=r"(r3) : "r"(addr));
}

__device__ __forceinline__ void cp16(uint32_t dst, const void* src, bool pred) {
    int sz = pred ? 16 : 0;   // src_size=0 -> zero-fill
    asm volatile("cp.async.cg.shared.global [%0], [%1], 16, %2;"
                 :: "r"(dst), "l"(src), "r"(sz));
}
#define CP_COMMIT() asm volatile("cp.async.commit_group;" ::: "memory")
#define CP_WAIT1()  asm volatile("cp.async.wait_group 1;" ::: "memory")

__global__ __launch_bounds__(256, 2) void k_gemm_mma(const float* __restrict__ bias,
                                                     float* __restrict__ out, int n) {
    extern __shared__ __half smem[];
    const int tid = threadIdx.x;
    const int wid = tid >> 5;
    const int lid = tid & 31;
    const int g   = lid >> 2;
    const int t   = lid & 3;
    const int wm  = wid & 1;
    const int wn  = wid >> 1;

    const int row0 = blockIdx.y * 128;
    const int n0   = blockIdx.x * 128;
    const int arows = min(128, n - row0);

    const int st_r  = tid >> 1;          // 0..127 (2 threads per row)
    const int st_c8 = (tid & 1) * 16;    // halves offset 0 or 16; each thread does 2 cp16/array

    const int lm_r = lid & 15;
    const int lm_c = (lid >> 4) * 8;

    const uint32_t smem_base = (uint32_t)__cvta_generic_to_shared(smem);

    float acc[4][4][4];
#pragma unroll
    for (int mf = 0; mf < 4; mf++)
#pragma unroll
        for (int nf = 0; nf < 4; nf++)
#pragma unroll
            for (int r = 0; r < 4; r++) acc[mf][nf][r] = 0.f;

    // issue stage s loading k-chunk kc
    auto issue = [&](int s, int kc) {
        const int kb = kc * 32;
        uint32_t aoff = smem_base + (uint32_t)(s * TILE_H + st_r * SAB_STRIDE + st_c8) * 2;
        uint32_t boff = smem_base + (uint32_t)((4 + s) * TILE_H + st_r * SAB_STRIDE + st_c8) * 2;
        bool av = st_r < arows;
        cp16(aoff,      &g_agg16[(size_t)(row0 + st_r) * D + kb + st_c8],     av);
        cp16(aoff + 16, &g_agg16[(size_t)(row0 + st_r) * D + kb + st_c8 + 8], av);
        cp16(boff,      &g_wt16[(size_t)(n0 + st_r) * D + kb + st_c8],        true);
        cp16(boff + 16, &g_wt16[(size_t)(n0 + st_r) * D + kb + st_c8 + 8],    true);
    };

    issue(0, 0); CP_COMMIT();
    issue(1, 1); CP_COMMIT();

    for (int kc = 0; kc < 8; kc++) {
        const int cur = kc & 3;
        CP_WAIT1();
        __syncthreads();
        const __half* cA = smem + cur * TILE_H;
        const __half* cB = smem + (4 + cur) * TILE_H;
#pragma unroll
        for (int ks = 0; ks < 2; ks++) {
            const int k0 = ks * 16;
            uint32_t af[4][4], bf[4][2];
#pragma unroll
            for (int mf = 0; mf < 4; mf++) {
                int mrow = wm * 64 + mf * 16 + lm_r;
                uint32_t addr = (uint32_t)__cvta_generic_to_shared(
                    &cA[mrow * SAB_STRIDE + k0 + lm_c]);
                ldsm_x4(af[mf][0], af[mf][1], af[mf][2], af[mf][3], addr);
            }
#pragma unroll
            for (int p = 0; p < 2; p++) {
                int nrow = wn * 32 + p * 16 + lm_r;
                uint32_t addr = (uint32_t)__cvta_generic_to_shared(
                    &cB[nrow * SAB_STRIDE + k0 + lm_c]);
                ldsm_x4(bf[2 * p][0], bf[2 * p + 1][0], bf[2 * p][1], bf[2 * p + 1][1], addr);
            }
#pragma unroll
            for (int mf = 0; mf < 4; mf++)
#pragma unroll
                for (int nf = 0; nf < 4; nf++)
                    mma_f16(acc[mf][nf], af[mf], bf[nf]);
        }
        if (kc + 2 < 8) issue((kc + 2) & 3, kc + 2);
        CP_COMMIT();
    }

#pragma unroll
    for (int mf = 0; mf < 4; mf++) {
        int r0 = row0 + wm * 64 + mf * 16 + g;
        int r1 = r0 + 8;
        float post0 = 0.f, post1 = 0.f;
        if (r0 < n) post0 = g_post[r0];
        if (r1 < n) post1 = g_post[r1];
#pragma unroll
        for (int nf = 0; nf < 4; nf++) {
            int c = n0 + wn * 32 + nf * 8 + t * 2;
            float2 b2 = *(const float2*)&bias[c];
            if (r0 < n) {
                float2 v;
                v.x = acc[mf][nf][0] * post0 + b2.x;
                v.y = acc[mf][nf][1] * post0 + b2.y;
                *(float2*)&out[(size_t)r0 * D + c] = v;
            }
            if (r1 < n) {
                float2 v;
                v.x = acc[mf][nf][2] * post1 + b2.x;
                v.y = acc[mf][nf][3] * post1 + b2.y;
                *(float2*)&out[(size_t)r1 * D + c] = v;
            }
        }
    }

    // ---- zero scratch counters for the NEXT replay ----
    if (blockIdx.x == 0) {
        for (int i = tid; i < 128; i += 256) {
            int r = row0 + i;
            if (r < n) { g_in_deg[r] = 0; g_out_deg[r] = 0; }
        }
        if (blockIdx.y == 0) {
            if (tid < 128) g_scan_state[tid] = 0ULL;
            if (tid == 128) g_scan_done = 0;
        }
    }
}

// ======================= launch =======================
extern "C" void kernel_launch(void* const* d_in, const int* in_sizes, int n_in,
                              void* d_out, int out_size) {
    const float* feat   = (const float*)d_in[0];
    const int*   src    = (const int*)d_in[1];
    const int*   dst    = (const int*)d_in[2];
    const float* weight = (const float*)d_in[3];
    const float* bias   = (const float*)d_in[4];
    float*       out    = (float*)d_out;

    int n = in_sizes[0] / D;   // 100000
    int e = in_sizes[1];       // 1600000

    int nb = (n + 1023) / 1024;
    int fb = (n * 32 + 1023) / 1024;
    int wb = 64;
    int eb = (e + 1023) / 1024;
    int degb = ((e + 1) / 2 + 255) / 256;

    static bool attr_set = false;
    if (!attr_set) {
        cudaFuncSetAttribute(k_gemm_mma, cudaFuncAttributeMaxDynamicSharedMemorySize,
                             SMEM_GEMM);
        attr_set = true;
    }

    k_deg<<<degb, 256>>>(src, dst, e);                                       // 0
    k_mid<<<nb + fb + wb + eb, 1024>>>((const float4*)feat, weight,
                                       src, dst, n, e, nb, fb);              // 1
    k_agg<<<1184, 256>>>(n, (n + 7) / 8);                                    // 2
    dim3 gg(2, (n + 127) / 128);
    k_gemm_mma<<<gg, 256, SMEM_GEMM>>>(bias, out, n);                        // 3  <- profiled
}